// round 7
// baseline (speedup 1.0000x reference)
#include <cuda_runtime.h>
#include <cuda_fp16.h>
#include <cstdint>

// Block-circulant linear via length-4 DFT diagonalization + Gauss 3-mult
// complex product: 5/16 of the dense GEMM work. fp16 operands (same 10-bit
// mantissa as tf32), f32 accumulation, fragment-order scratch layouts.
//
//   u0=a+b+c+d, u1r=a-c, u1i=d-b, u2=a-b+c-d, u1s=u1r+u1i   (per x block)
//   P0=Fe0/4, P2=Fe2/4, P1r=(e0-e2)/2, P1i=(e3-e1)/2, Pd=P1i-P1r, Ps=P1i+P1r
//   F0 = sum P0*u0 ; F2 = sum P2*u2
//   K1 = sum P1r*u1s ; K2 = sum Pd*u1r ; K3 = sum Ps*u1i
//   F1r = K1-K3 ; F1i = K1+K2
//   o0=F0+F1r+F2  o1=F0-F1i-F2  o2=F0-F1r+F2  o3=F0+F1i-F2

#define B_DIM 4096
#define GX 1024
#define GY 1024
#define N_DIM 4096

// A tile (per bmt,kt): [c(5)][mt(8)][kstep(2)][lane(32)][reg(4)] f16x2 = 40KB
//   comp order: 0=u0, 1=u2, 2=u1s, 3=u1r, 4=u1i
// E tile (per yt, kt): [p(5)][nt(8)][kstep(2)][lane(32)][reg(2)] f16x2 = 20KB
//   plane order: 0=P0, 1=P2, 2=P1r, 3=Pd, 4=Ps
#define A_TILE_U32 10240
#define E_TILE_U32 5120
__device__ uint32_t g_U[(size_t)32 * 32 * A_TILE_U32];   // 40 MB
__device__ uint32_t g_E[(size_t)16 * 32 * E_TILE_U32];   // 10 MB

__device__ __forceinline__ uint32_t pack_h2(float lo, float hi) {
    __half2 h = __floats2half2_rn(lo, hi);
    return *reinterpret_cast<uint32_t*>(&h);
}

// ---------------------------------------------------------------------------
// transform_x: thread = (bmt, kt, mt, lane); produces the exact fp16 A frags.
// ---------------------------------------------------------------------------
__global__ void __launch_bounds__(256) transform_x_kernel(const float* __restrict__ xin) {
    int t = blockIdx.x * blockDim.x + threadIdx.x;   // 262144
    int lane = t & 31;
    int mt   = (t >> 5) & 7;
    int kt   = (t >> 8) & 31;
    int bmt  = t >> 13;
    int g = lane >> 2, tg = lane & 3;

    uint32_t regs[5][2][4];   // [c][kstep][reg]
    #pragma unroll
    for (int hi = 0; hi < 2; hi++) {
        int b = bmt * 128 + mt * 16 + g + 8 * hi;
        const float4* xr = reinterpret_cast<const float4*>(xin) + (size_t)b * GX;
        #pragma unroll
        for (int kstep = 0; kstep < 2; kstep++) {
            #pragma unroll
            for (int khi = 0; khi < 2; khi++) {
                int xb = kt * 32 + kstep * 16 + khi * 8 + 2 * tg;
                float4 f0 = xr[xb];
                float4 f1 = xr[xb + 1];
                float ue[5], uo[5];
                float e1r = f0.x - f0.z,  o1r = f1.x - f1.z;
                float e1i = f0.w - f0.y,  o1i = f1.w - f1.y;
                ue[0] = f0.x + f0.y + f0.z + f0.w;  uo[0] = f1.x + f1.y + f1.z + f1.w;
                ue[1] = f0.x - f0.y + f0.z - f0.w;  uo[1] = f1.x - f1.y + f1.z - f1.w;
                ue[2] = e1r + e1i;                  uo[2] = o1r + o1i;
                ue[3] = e1r;                        uo[3] = o1r;
                ue[4] = e1i;                        uo[4] = o1i;
                int r = hi + 2 * khi;
                #pragma unroll
                for (int c = 0; c < 5; c++) regs[c][kstep][r] = pack_h2(ue[c], uo[c]);
            }
        }
    }
    uint32_t* tile = g_U + (size_t)(bmt * 32 + kt) * A_TILE_U32;
    #pragma unroll
    for (int c = 0; c < 5; c++)
        #pragma unroll
        for (int kstep = 0; kstep < 2; kstep++) {
            int idx = (((c * 8 + mt) * 2 + kstep) * 32 + lane) * 4;
            *reinterpret_cast<uint4*>(tile + idx) =
                make_uint4(regs[c][kstep][0], regs[c][kstep][1],
                           regs[c][kstep][2], regs[c][kstep][3]);
        }
}

// ---------------------------------------------------------------------------
// transform_e: thread = (yt, kt, nt, lane); produces the exact fp16 B frags.
// ---------------------------------------------------------------------------
__global__ void __launch_bounds__(256) transform_e_kernel(const float* __restrict__ eig) {
    int t = blockIdx.x * blockDim.x + threadIdx.x;   // 131072
    int lane = t & 31;
    int nt   = (t >> 5) & 7;
    int kt   = (t >> 8) & 31;
    int yt   = t >> 13;
    int g = lane >> 2, tg = lane & 3;

    int y = yt * 64 + nt * 8 + g;
    const float4* er = reinterpret_cast<const float4*>(eig) + (size_t)y * GX;

    uint32_t regs[5][2][2];   // [p][kstep][reg=khi]
    #pragma unroll
    for (int kstep = 0; kstep < 2; kstep++) {
        #pragma unroll
        for (int khi = 0; khi < 2; khi++) {
            int xb = kt * 32 + kstep * 16 + khi * 8 + 2 * tg;
            float4 e0 = er[xb];
            float4 e1 = er[xb + 1];
            float pe[5], po[5];
            float er0 = (e0.x - e0.z) * 0.5f,  or0 = (e1.x - e1.z) * 0.5f;   // P1r
            float ei0 = (e0.w - e0.y) * 0.5f,  oi0 = (e1.w - e1.y) * 0.5f;   // P1i
            pe[0] = (e0.x + e0.y + e0.z + e0.w) * 0.25f;
            po[0] = (e1.x + e1.y + e1.z + e1.w) * 0.25f;
            pe[1] = (e0.x - e0.y + e0.z - e0.w) * 0.25f;
            po[1] = (e1.x - e1.y + e1.z - e1.w) * 0.25f;
            pe[2] = er0;            po[2] = or0;
            pe[3] = ei0 - er0;      po[3] = oi0 - or0;
            pe[4] = ei0 + er0;      po[4] = oi0 + or0;
            #pragma unroll
            for (int p = 0; p < 5; p++) regs[p][kstep][khi] = pack_h2(pe[p], po[p]);
        }
    }
    uint32_t* tile = g_E + (size_t)(yt * 32 + kt) * E_TILE_U32;
    #pragma unroll
    for (int p = 0; p < 5; p++)
        #pragma unroll
        for (int kstep = 0; kstep < 2; kstep++) {
            int idx = (((p * 8 + nt) * 2 + kstep) * 32 + lane) * 2;
            *reinterpret_cast<uint2*>(tile + idx) =
                make_uint2(regs[p][kstep][0], regs[p][kstep][1]);
        }
}

// ---------------------------------------------------------------------------
// GEMM: CTA 128(b) x 64(gy blocks), 8 warps (4m x 2n), warp 32m x 32gy.
// fp16 m16n8k16 MMA, 5 uniform accumulator sets, 3-stage cp.async pipeline.
// ---------------------------------------------------------------------------
#define STAGE_U32 (A_TILE_U32 + E_TILE_U32)       // 15360 (60KB)
#define STAGES 3
#define SMEM_BYTES (STAGES * STAGE_U32 * 4)       // 184320

__global__ void __launch_bounds__(256, 1) gemm_freq_kernel(float* __restrict__ out) {
    extern __shared__ uint32_t smem[];

    const int tid  = threadIdx.x;
    const int yt   = blockIdx.x;
    const int bmt  = blockIdx.y;
    const int bgy0 = yt * 64;
    const int bm0  = bmt * 128;

    const int warp  = tid >> 5;
    const int lane  = tid & 31;
    const int g     = lane >> 2;
    const int tg    = lane & 3;
    const int warpM = warp & 3;
    const int warpN = warp >> 2;

    // acc sets: 0=F0, 1=F2, 2=K1, 3=K2, 4=K3
    float acc[5][2][4][4];
    #pragma unroll
    for (int s = 0; s < 5; s++)
        #pragma unroll
        for (int mi = 0; mi < 2; mi++)
            #pragma unroll
            for (int ni = 0; ni < 4; ni++)
                #pragma unroll
                for (int q = 0; q < 4; q++) acc[s][mi][ni][q] = 0.0f;

    const uint32_t* gA = g_U + (size_t)bmt * 32 * A_TILE_U32;
    const uint32_t* gE = g_E + (size_t)yt * 32 * E_TILE_U32;

    auto load_tile = [&](int kt, int buf) {
        uint32_t* baseA = smem + buf * STAGE_U32;
        uint32_t* baseE = baseA + A_TILE_U32;
        const uint32_t* sA = gA + (size_t)kt * A_TILE_U32;
        const uint32_t* sE = gE + (size_t)kt * E_TILE_U32;
        #pragma unroll
        for (int j = 0; j < 10; j++) {
            int ck = tid + j * 256;
            uint32_t dst = (uint32_t)__cvta_generic_to_shared(baseA + ck * 4);
            asm volatile("cp.async.cg.shared.global [%0], [%1], 16;\n"
                         :: "r"(dst), "l"(sA + ck * 4) : "memory");
        }
        #pragma unroll
        for (int j = 0; j < 5; j++) {
            int ck = tid + j * 256;
            uint32_t dst = (uint32_t)__cvta_generic_to_shared(baseE + ck * 4);
            asm volatile("cp.async.cg.shared.global [%0], [%1], 16;\n"
                         :: "r"(dst), "l"(sE + ck * 4) : "memory");
        }
        asm volatile("cp.async.commit_group;\n" ::: "memory");
    };

    const int NK = 32;
    load_tile(0, 0);
    load_tile(1, 1);

    #define MMA(ACC, AF, B0, B1)                                                  \
        asm volatile(                                                             \
            "mma.sync.aligned.m16n8k16.row.col.f32.f16.f16.f32 "                  \
            "{%0,%1,%2,%3}, {%4,%5,%6,%7}, {%8,%9}, {%0,%1,%2,%3};\n"             \
            : "+f"((ACC)[0]), "+f"((ACC)[1]), "+f"((ACC)[2]), "+f"((ACC)[3])      \
            : "r"((AF).x), "r"((AF).y), "r"((AF).z), "r"((AF).w),                 \
              "r"(B0), "r"(B1))

    for (int kt = 0; kt < NK; kt++) {
        if (kt + 1 < NK) {
            asm volatile("cp.async.wait_group 1;\n" ::: "memory");
        } else {
            asm volatile("cp.async.wait_group 0;\n" ::: "memory");
        }
        __syncthreads();
        if (kt + 2 < NK) load_tile(kt + 2, (kt + 2) % STAGES);

        const uint32_t* base = smem + (kt % STAGES) * STAGE_U32;
        const uint4* A4 = reinterpret_cast<const uint4*>(base);
        const uint2* E2 = reinterpret_cast<const uint2*>(base + A_TILE_U32);

        #pragma unroll
        for (int kstep = 0; kstep < 2; kstep++) {
            uint4 uf[5][2];
            #pragma unroll
            for (int c = 0; c < 5; c++)
                #pragma unroll
                for (int mi = 0; mi < 2; mi++)
                    uf[c][mi] = A4[((c * 8 + warpM * 2 + mi) * 2 + kstep) * 32 + lane];

            #pragma unroll
            for (int ni = 0; ni < 4; ni++) {
                uint2 ef[5];
                #pragma unroll
                for (int p = 0; p < 5; p++)
                    ef[p] = E2[((p * 8 + warpN * 4 + ni) * 2 + kstep) * 32 + lane];

                #pragma unroll
                for (int mi = 0; mi < 2; mi++) {
                    #pragma unroll
                    for (int s = 0; s < 5; s++)
                        MMA(acc[s][mi][ni], uf[s][mi], ef[s].x, ef[s].y);
                }
            }
        }
    }
    #undef MMA

    // Epilogue: Gauss recombine + inverse-DFT butterfly; one float4 per block.
    #pragma unroll
    for (int mi = 0; mi < 2; mi++) {
        #pragma unroll
        for (int ni = 0; ni < 4; ni++) {
            #pragma unroll
            for (int h = 0; h < 2; h++) {
                #pragma unroll
                for (int q = 0; q < 2; q++) {
                    int row = bm0 + warpM * 32 + mi * 16 + g + h * 8;
                    int gy  = bgy0 + warpN * 32 + ni * 8 + 2 * tg + q;
                    float F0 = acc[0][mi][ni][2 * h + q];
                    float F2 = acc[1][mi][ni][2 * h + q];
                    float K1 = acc[2][mi][ni][2 * h + q];
                    float K2 = acc[3][mi][ni][2 * h + q];
                    float K3 = acc[4][mi][ni][2 * h + q];
                    float F1r = K1 - K3;
                    float F1i = K1 + K2;
                    float4 o;
                    o.x = F0 + F1r + F2;
                    o.y = F0 - F1i - F2;
                    o.z = F0 - F1r + F2;
                    o.w = F0 + F1i - F2;
                    *reinterpret_cast<float4*>(out + (size_t)row * N_DIM + 4 * gy) = o;
                }
            }
        }
    }
}

// ---------------------------------------------------------------------------
extern "C" void kernel_launch(void* const* d_in, const int* in_sizes, int n_in,
                              void* d_out, int out_size) {
    const float* x   = (const float*)d_in[0];   // (4096, 4096) f32
    const float* eig = (const float*)d_in[1];   // (1024, 1024, 4) f32
    float* out       = (float*)d_out;           // (4096, 4096) f32

    cudaFuncSetAttribute(gemm_freq_kernel,
                         cudaFuncAttributeMaxDynamicSharedMemorySize, SMEM_BYTES);

    transform_x_kernel<<<262144 / 256, 256>>>(x);
    transform_e_kernel<<<131072 / 256, 256>>>(eig);

    dim3 grid(GY / 64, B_DIM / 128);   // (16, 32) = 512 CTAs
    gemm_freq_kernel<<<grid, 256, SMEM_BYTES>>>(out);
    (void)in_sizes; (void)n_in; (void)out_size;
}

// round 8
// speedup vs baseline: 1.2701x; 1.2701x over previous
#include <cuda_runtime.h>
#include <cuda_fp16.h>
#include <cstdint>

// Block-circulant linear via length-4 DFT diagonalization (6/16 dense work),
// fp16 operands, f32 accumulation, fragment-order scratch.
// R8: cp.async.bulk + mbarrier pipeline, 4 sub-tiles/CTA (single wave),
//     paired-E fragment layout.
//
//   u0=a+b+c+d, u1r=a-c, u1i=d-b, u2=a-b+c-d  (per x block)
//   P0=Fe0/4, P2=Fe2/4, P1r=(e0-e2)/2, P1i=(e3-e1)/2, P1n=-P1i
//   F0=sum P0*u0 ; F2=sum P2*u2
//   F1r=sum P1r*u1r + P1n*u1i ; F1i=sum P1i*u1r + P1r*u1i
//   o0=F0+F1r+F2  o1=F0-F1i-F2  o2=F0-F1r+F2  o3=F0+F1i-F2

#define B_DIM 4096
#define GX 1024
#define GY 1024
#define N_DIM 4096

// A tile (per bmt,kt): [c(4)][mt(8)][kstep(2)][lane(32)][reg(4)] f16x2 = 32KB
// E tile (per yt, kt): [p(5)][ntp(4)][kstep(2)][lane(32)][4] f16x2 = 20KB
//   (uint4 per lane = fragments for nt=2*ntp and 2*ntp+1)
#define A_TILE_U32 8192
#define E_TILE_U32 5120
__device__ uint32_t g_U[(size_t)32 * 32 * A_TILE_U32];   // 32 MB
__device__ uint32_t g_E[(size_t)16 * 32 * E_TILE_U32];   // 10 MB

__device__ __forceinline__ uint32_t pack_h2(float lo, float hi) {
    __half2 h = __floats2half2_rn(lo, hi);
    return *reinterpret_cast<uint32_t*>(&h);
}
__device__ __forceinline__ uint32_t smem_u32(const void* p) {
    uint32_t a;
    asm("{ .reg .u64 t; cvta.to.shared.u64 t, %1; cvt.u32.u64 %0, t; }" : "=r"(a) : "l"(p));
    return a;
}
__device__ __forceinline__ void mbar_init(uint32_t a, uint32_t cnt) {
    asm volatile("mbarrier.init.shared.b64 [%0], %1;" :: "r"(a), "r"(cnt) : "memory");
}
__device__ __forceinline__ void mbar_expect_tx(uint32_t a, uint32_t tx) {
    asm volatile("mbarrier.arrive.expect_tx.shared.b64 _, [%0], %1;" :: "r"(a), "r"(tx) : "memory");
}
__device__ __forceinline__ void mbar_arrive(uint32_t a) {
    asm volatile("mbarrier.arrive.shared.b64 _, [%0];" :: "r"(a) : "memory");
}
__device__ __forceinline__ void mbar_wait(uint32_t a, uint32_t parity) {
    asm volatile(
        "{\n\t.reg .pred P;\n\t"
        "W%=:\n\t"
        "mbarrier.try_wait.parity.shared.b64 P, [%0], %1;\n\t"
        "@!P bra W%=;\n\t}"
        :: "r"(a), "r"(parity) : "memory");
}
__device__ __forceinline__ void bulk_g2s(uint32_t dst, const void* src, uint32_t bytes, uint32_t mbar) {
    asm volatile(
        "cp.async.bulk.shared::cta.global.mbarrier::complete_tx::bytes [%0], [%1], %2, [%3];"
        :: "r"(dst), "l"(src), "r"(bytes), "r"(mbar) : "memory");
}

// ---------------------------------------------------------------------------
// transform_x: thread = (bmt, kt, mt, lane); exact fp16 A fragments.
// ---------------------------------------------------------------------------
__global__ void __launch_bounds__(256) transform_x_kernel(const float* __restrict__ xin) {
    int t = blockIdx.x * blockDim.x + threadIdx.x;   // 262144
    int lane = t & 31;
    int mt   = (t >> 5) & 7;
    int kt   = (t >> 8) & 31;
    int bmt  = t >> 13;
    int g = lane >> 2, tg = lane & 3;

    uint32_t regs[4][2][4];   // [c][kstep][reg]
    #pragma unroll
    for (int hi = 0; hi < 2; hi++) {
        int b = bmt * 128 + mt * 16 + g + 8 * hi;
        const float4* xr = reinterpret_cast<const float4*>(xin) + (size_t)b * GX;
        #pragma unroll
        for (int kstep = 0; kstep < 2; kstep++) {
            #pragma unroll
            for (int khi = 0; khi < 2; khi++) {
                int xb = kt * 32 + kstep * 16 + khi * 8 + 2 * tg;
                float4 f0 = xr[xb];
                float4 f1 = xr[xb + 1];
                float ue[4], uo[4];
                ue[0] = f0.x + f0.y + f0.z + f0.w;  uo[0] = f1.x + f1.y + f1.z + f1.w;
                ue[1] = f0.x - f0.z;                uo[1] = f1.x - f1.z;
                ue[2] = f0.w - f0.y;                uo[2] = f1.w - f1.y;
                ue[3] = f0.x - f0.y + f0.z - f0.w;  uo[3] = f1.x - f1.y + f1.z - f1.w;
                int r = hi + 2 * khi;
                #pragma unroll
                for (int c = 0; c < 4; c++) regs[c][kstep][r] = pack_h2(ue[c], uo[c]);
            }
        }
    }
    uint32_t* tile = g_U + (size_t)(bmt * 32 + kt) * A_TILE_U32;
    #pragma unroll
    for (int c = 0; c < 4; c++)
        #pragma unroll
        for (int kstep = 0; kstep < 2; kstep++) {
            int idx = (((c * 8 + mt) * 2 + kstep) * 32 + lane) * 4;
            *reinterpret_cast<uint4*>(tile + idx) =
                make_uint4(regs[c][kstep][0], regs[c][kstep][1],
                           regs[c][kstep][2], regs[c][kstep][3]);
        }
}

// ---------------------------------------------------------------------------
// transform_e: thread = (yt, kt, nt, lane); paired-nt fp16 B fragments.
// ---------------------------------------------------------------------------
__global__ void __launch_bounds__(256) transform_e_kernel(const float* __restrict__ eig) {
    int t = blockIdx.x * blockDim.x + threadIdx.x;   // 131072
    int lane = t & 31;
    int nt   = (t >> 5) & 7;
    int kt   = (t >> 8) & 31;
    int yt   = t >> 13;
    int g = lane >> 2, tg = lane & 3;

    int y = yt * 64 + nt * 8 + g;
    const float4* er = reinterpret_cast<const float4*>(eig) + (size_t)y * GX;

    uint32_t regs[5][2][2];   // [p][kstep][khi]
    #pragma unroll
    for (int kstep = 0; kstep < 2; kstep++) {
        #pragma unroll
        for (int khi = 0; khi < 2; khi++) {
            int xb = kt * 32 + kstep * 16 + khi * 8 + 2 * tg;
            float4 e0 = er[xb];
            float4 e1 = er[xb + 1];
            float pe[5], po[5];
            pe[0] = (e0.x + e0.y + e0.z + e0.w) * 0.25f;
            po[0] = (e1.x + e1.y + e1.z + e1.w) * 0.25f;
            pe[1] = (e0.x - e0.y + e0.z - e0.w) * 0.25f;
            po[1] = (e1.x - e1.y + e1.z - e1.w) * 0.25f;
            pe[2] = (e0.x - e0.z) * 0.5f;   po[2] = (e1.x - e1.z) * 0.5f;
            pe[3] = (e0.w - e0.y) * 0.5f;   po[3] = (e1.w - e1.y) * 0.5f;
            pe[4] = -pe[3];                 po[4] = -po[3];
            #pragma unroll
            for (int p = 0; p < 5; p++) regs[p][kstep][khi] = pack_h2(pe[p], po[p]);
        }
    }
    uint32_t* tile = g_E + (size_t)(yt * 32 + kt) * E_TILE_U32;
    #pragma unroll
    for (int p = 0; p < 5; p++)
        #pragma unroll
        for (int kstep = 0; kstep < 2; kstep++) {
            // paired layout: [p][ntp(4)][kstep][lane][4], halves selected by nt&1
            int idx = (((p * 4 + (nt >> 1)) * 2 + kstep) * 32 + lane) * 4 + (nt & 1) * 2;
            *reinterpret_cast<uint2*>(tile + idx) =
                make_uint2(regs[p][kstep][0], regs[p][kstep][1]);
        }
}

// ---------------------------------------------------------------------------
// GEMM: CTA owns 2 bmt x 2 yt sub-tiles (256b x 256 out-cols region).
// Per sub-tile: 128b x 64 gy-blocks; 8 warps (4m x 2n), warp 32b x 32gy.
// cp.async.bulk + mbarrier 3-stage pipeline, continuous across sub-tiles.
// ---------------------------------------------------------------------------
#define STAGE_U32 (A_TILE_U32 + E_TILE_U32)       // 13312 (53248 B)
#define STAGES 3
#define HDR_U32 256                               // 1024 B header
#define SMEM_BYTES ((HDR_U32 + STAGES * STAGE_U32) * 4)   // 160768

__global__ void __launch_bounds__(256, 1) gemm_freq_kernel(float* __restrict__ out) {
    extern __shared__ uint32_t smem[];
    const uint32_t sbase  = smem_u32(smem);
    const uint32_t full0  = sbase;            // full[s]  at +8s
    const uint32_t empty0 = sbase + 32;       // empty[s] at +8s
    const uint32_t stage0 = sbase + HDR_U32 * 4;

    const int tid  = threadIdx.x;
    const int ytp  = blockIdx.x;   // 0..7   -> yt  = 2*ytp + ysel
    const int bmtp = blockIdx.y;   // 0..15  -> bmt = 2*bmtp + bsel

    const int warp  = tid >> 5;
    const int lane  = tid & 31;
    const int g     = lane >> 2;
    const int tg    = lane & 3;
    const int warpM = warp & 3;
    const int warpN = warp >> 2;

    if (tid == 0) {
        #pragma unroll
        for (int s = 0; s < STAGES; s++) {
            mbar_init(full0 + 8 * s, 1);
            mbar_init(empty0 + 8 * s, 8);
        }
    }
    __syncthreads();

    // producer helper (tid 0 only): load global iteration gi into stage gi%3
    auto produce = [&](int gi) {
        int t2 = gi >> 5, kt2 = gi & 31;
        int bsel = t2 >> 1, ysel = bsel ^ (t2 & 1);
        const uint32_t* sA = g_U + (size_t)((bmtp * 2 + bsel) * 32 + kt2) * A_TILE_U32;
        const uint32_t* sE = g_E + (size_t)((ytp * 2 + ysel) * 32 + kt2) * E_TILE_U32;
        int s2 = gi % 3, r2 = gi / 3;
        if (r2 >= 1) mbar_wait(empty0 + 8 * s2, (uint32_t)(r2 - 1) & 1u);
        uint32_t fb = full0 + 8 * s2;
        mbar_expect_tx(fb, STAGE_U32 * 4);
        uint32_t sa = stage0 + s2 * (STAGE_U32 * 4);
        bulk_g2s(sa, sA, A_TILE_U32 * 4, fb);
        bulk_g2s(sa + A_TILE_U32 * 4, sE, E_TILE_U32 * 4, fb);
    };

    if (tid == 0) { produce(0); produce(1); }

    #define MMA(ACC, AF, B0, B1)                                                  \
        asm volatile(                                                             \
            "mma.sync.aligned.m16n8k16.row.col.f32.f16.f16.f32 "                  \
            "{%0,%1,%2,%3}, {%4,%5,%6,%7}, {%8,%9}, {%0,%1,%2,%3};\n"             \
            : "+f"((ACC)[0]), "+f"((ACC)[1]), "+f"((ACC)[2]), "+f"((ACC)[3])      \
            : "r"((AF).x), "r"((AF).y), "r"((AF).z), "r"((AF).w),                 \
              "r"(B0), "r"(B1))

    for (int t = 0; t < 4; t++) {
        const int bsel = t >> 1, ysel = bsel ^ (t & 1);
        const int bm0  = (bmtp * 2 + bsel) * 128;
        const int bgy0 = (ytp * 2 + ysel) * 64;

        float acc[4][2][4][4];   // [set][mi][ni][frag]  0=F0 1=F2 2=F1r 3=F1i
        #pragma unroll
        for (int s = 0; s < 4; s++)
            #pragma unroll
            for (int mi = 0; mi < 2; mi++)
                #pragma unroll
                for (int ni = 0; ni < 4; ni++)
                    #pragma unroll
                    for (int q = 0; q < 4; q++) acc[s][mi][ni][q] = 0.0f;

        for (int kt = 0; kt < 32; kt++) {
            int gi = t * 32 + kt;
            if (tid == 0 && gi + 2 < 128) produce(gi + 2);

            int s = gi % 3;
            mbar_wait(full0 + 8 * s, (uint32_t)(gi / 3) & 1u);

            const uint32_t* base = smem + HDR_U32 + s * STAGE_U32;
            const uint4* A4 = reinterpret_cast<const uint4*>(base);
            const uint4* E4 = reinterpret_cast<const uint4*>(base + A_TILE_U32);

            #pragma unroll
            for (int kstep = 0; kstep < 2; kstep++) {
                uint4 uf[4][2];
                #pragma unroll
                for (int c = 0; c < 4; c++)
                    #pragma unroll
                    for (int mi = 0; mi < 2; mi++)
                        uf[c][mi] = A4[((c * 8 + warpM * 2 + mi) * 2 + kstep) * 32 + lane];

                uint2 ef[5][4];
                #pragma unroll
                for (int p = 0; p < 5; p++)
                    #pragma unroll
                    for (int nip = 0; nip < 2; nip++) {
                        uint4 e4 = E4[((p * 4 + warpN * 2 + nip) * 2 + kstep) * 32 + lane];
                        ef[p][2 * nip]     = make_uint2(e4.x, e4.y);
                        ef[p][2 * nip + 1] = make_uint2(e4.z, e4.w);
                    }

                #pragma unroll
                for (int ni = 0; ni < 4; ni++) {
                    #pragma unroll
                    for (int mi = 0; mi < 2; mi++) {
                        MMA(acc[0][mi][ni], uf[0][mi], ef[0][ni].x, ef[0][ni].y);  // F0 +=P0 *u0
                        MMA(acc[1][mi][ni], uf[3][mi], ef[1][ni].x, ef[1][ni].y);  // F2 +=P2 *u2
                        MMA(acc[2][mi][ni], uf[1][mi], ef[2][ni].x, ef[2][ni].y);  // F1r+=P1r*u1r
                        MMA(acc[2][mi][ni], uf[2][mi], ef[4][ni].x, ef[4][ni].y);  // F1r+=P1n*u1i
                        MMA(acc[3][mi][ni], uf[1][mi], ef[3][ni].x, ef[3][ni].y);  // F1i+=P1i*u1r
                        MMA(acc[3][mi][ni], uf[2][mi], ef[2][ni].x, ef[2][ni].y);  // F1i+=P1r*u1i
                    }
                }
            }
            if (lane == 0) mbar_arrive(empty0 + 8 * s);
        }

        // Epilogue for this sub-tile: inverse-DFT butterfly, float4 stores.
        #pragma unroll
        for (int mi = 0; mi < 2; mi++) {
            #pragma unroll
            for (int ni = 0; ni < 4; ni++) {
                #pragma unroll
                for (int h = 0; h < 2; h++) {
                    #pragma unroll
                    for (int q = 0; q < 2; q++) {
                        int row = bm0 + warpM * 32 + mi * 16 + g + h * 8;
                        int gy  = bgy0 + warpN * 32 + ni * 8 + 2 * tg + q;
                        float F0  = acc[0][mi][ni][2 * h + q];
                        float F2  = acc[1][mi][ni][2 * h + q];
                        float F1r = acc[2][mi][ni][2 * h + q];
                        float F1i = acc[3][mi][ni][2 * h + q];
                        float4 o;
                        o.x = F0 + F1r + F2;
                        o.y = F0 - F1i - F2;
                        o.z = F0 - F1r + F2;
                        o.w = F0 + F1i - F2;
                        *reinterpret_cast<float4*>(out + (size_t)row * N_DIM + 4 * gy) = o;
                    }
                }
            }
        }
    }
    #undef MMA
}

// ---------------------------------------------------------------------------
extern "C" void kernel_launch(void* const* d_in, const int* in_sizes, int n_in,
                              void* d_out, int out_size) {
    const float* x   = (const float*)d_in[0];   // (4096, 4096) f32
    const float* eig = (const float*)d_in[1];   // (1024, 1024, 4) f32
    float* out       = (float*)d_out;           // (4096, 4096) f32

    cudaFuncSetAttribute(gemm_freq_kernel,
                         cudaFuncAttributeMaxDynamicSharedMemorySize, SMEM_BYTES);

    transform_x_kernel<<<262144 / 256, 256>>>(x);
    transform_e_kernel<<<131072 / 256, 256>>>(eig);

    dim3 grid(8, 16);   // 128 CTAs, each 2 bmt x 2 yt sub-tiles => single wave
    gemm_freq_kernel<<<grid, 256, SMEM_BYTES>>>(out);
    (void)in_sizes; (void)n_in; (void)out_size;
}

// round 9
// speedup vs baseline: 1.3304x; 1.0475x over previous
#include <cuda_runtime.h>
#include <cuda_fp16.h>
#include <cstdint>

// Block-circulant linear via length-4 DFT diagonalization (6/16 dense work),
// fp16 operands, f32 accumulation, fragment-order scratch.
// R9: merged transform kernel, 4-stage cp.async.bulk + mbarrier ring
//     (prefetch depth 3), 4 sub-tiles/CTA single-wave GEMM.
//
//   u0=a+b+c+d, u1r=a-c, u1i=d-b, u2=a-b+c-d  (per x block)
//   P0=Fe0/4, P2=Fe2/4, P1r=(e0-e2)/2, P1i=(e3-e1)/2, P1n=-P1i
//   F0=sum P0*u0 ; F2=sum P2*u2
//   F1r=sum P1r*u1r + P1n*u1i ; F1i=sum P1i*u1r + P1r*u1i
//   o0=F0+F1r+F2  o1=F0-F1i-F2  o2=F0-F1r+F2  o3=F0+F1i-F2

#define B_DIM 4096
#define GX 1024
#define GY 1024
#define N_DIM 4096

// A tile (per bmt,kt): [c(4)][mt(8)][kstep(2)][lane(32)][reg(4)] f16x2 = 32KB
// E tile (per yt, kt): [p(5)][ntp(4)][kstep(2)][lane(32)][4] f16x2 = 20KB
#define A_TILE_U32 8192
#define E_TILE_U32 5120
__device__ uint32_t g_U[(size_t)32 * 32 * A_TILE_U32];   // 32 MB
__device__ uint32_t g_E[(size_t)16 * 32 * E_TILE_U32];   // 10 MB

__device__ __forceinline__ uint32_t pack_h2(float lo, float hi) {
    __half2 h = __floats2half2_rn(lo, hi);
    return *reinterpret_cast<uint32_t*>(&h);
}
__device__ __forceinline__ uint32_t smem_u32(const void* p) {
    uint32_t a;
    asm("{ .reg .u64 t; cvta.to.shared.u64 t, %1; cvt.u32.u64 %0, t; }" : "=r"(a) : "l"(p));
    return a;
}
__device__ __forceinline__ void mbar_init(uint32_t a, uint32_t cnt) {
    asm volatile("mbarrier.init.shared.b64 [%0], %1;" :: "r"(a), "r"(cnt) : "memory");
}
__device__ __forceinline__ void mbar_expect_tx(uint32_t a, uint32_t tx) {
    asm volatile("mbarrier.arrive.expect_tx.shared.b64 _, [%0], %1;" :: "r"(a), "r"(tx) : "memory");
}
__device__ __forceinline__ void mbar_arrive(uint32_t a) {
    asm volatile("mbarrier.arrive.shared.b64 _, [%0];" :: "r"(a) : "memory");
}
__device__ __forceinline__ void mbar_wait(uint32_t a, uint32_t parity) {
    asm volatile(
        "{\n\t.reg .pred P;\n\t"
        "W%=:\n\t"
        "mbarrier.try_wait.parity.shared.b64 P, [%0], %1;\n\t"
        "@!P bra W%=;\n\t}"
        :: "r"(a), "r"(parity) : "memory");
}
__device__ __forceinline__ void bulk_g2s(uint32_t dst, const void* src, uint32_t bytes, uint32_t mbar) {
    asm volatile(
        "cp.async.bulk.shared::cta.global.mbarrier::complete_tx::bytes [%0], [%1], %2, [%3];"
        :: "r"(dst), "l"(src), "r"(bytes), "r"(mbar) : "memory");
}

// ---------------------------------------------------------------------------
// Merged transform kernel: blocks [0,1024) do X, [1024,1536) do E.
// ---------------------------------------------------------------------------
__global__ void __launch_bounds__(256) transform_kernel(
    const float* __restrict__ xin, const float* __restrict__ eig) {
    if (blockIdx.x < 1024) {
        // ---- X path: thread = (bmt, kt, mt, lane) ----
        int t = blockIdx.x * 256 + threadIdx.x;   // 262144
        int lane = t & 31;
        int mt   = (t >> 5) & 7;
        int kt   = (t >> 8) & 31;
        int bmt  = t >> 13;
        int g = lane >> 2, tg = lane & 3;

        uint32_t regs[4][2][4];
        #pragma unroll
        for (int hi = 0; hi < 2; hi++) {
            int b = bmt * 128 + mt * 16 + g + 8 * hi;
            const float4* xr = reinterpret_cast<const float4*>(xin) + (size_t)b * GX;
            #pragma unroll
            for (int kstep = 0; kstep < 2; kstep++) {
                #pragma unroll
                for (int khi = 0; khi < 2; khi++) {
                    int xb = kt * 32 + kstep * 16 + khi * 8 + 2 * tg;
                    float4 f0 = xr[xb];
                    float4 f1 = xr[xb + 1];
                    float ue[4], uo[4];
                    ue[0] = f0.x + f0.y + f0.z + f0.w;  uo[0] = f1.x + f1.y + f1.z + f1.w;
                    ue[1] = f0.x - f0.z;                uo[1] = f1.x - f1.z;
                    ue[2] = f0.w - f0.y;                uo[2] = f1.w - f1.y;
                    ue[3] = f0.x - f0.y + f0.z - f0.w;  uo[3] = f1.x - f1.y + f1.z - f1.w;
                    int r = hi + 2 * khi;
                    #pragma unroll
                    for (int c = 0; c < 4; c++) regs[c][kstep][r] = pack_h2(ue[c], uo[c]);
                }
            }
        }
        uint32_t* tile = g_U + (size_t)(bmt * 32 + kt) * A_TILE_U32;
        #pragma unroll
        for (int c = 0; c < 4; c++)
            #pragma unroll
            for (int kstep = 0; kstep < 2; kstep++) {
                int idx = (((c * 8 + mt) * 2 + kstep) * 32 + lane) * 4;
                *reinterpret_cast<uint4*>(tile + idx) =
                    make_uint4(regs[c][kstep][0], regs[c][kstep][1],
                               regs[c][kstep][2], regs[c][kstep][3]);
            }
    } else {
        // ---- E path: thread = (yt, kt, nt, lane) ----
        int t = (blockIdx.x - 1024) * 256 + threadIdx.x;   // 131072
        int lane = t & 31;
        int nt   = (t >> 5) & 7;
        int kt   = (t >> 8) & 31;
        int yt   = t >> 13;
        int g = lane >> 2, tg = lane & 3;

        int y = yt * 64 + nt * 8 + g;
        const float4* er = reinterpret_cast<const float4*>(eig) + (size_t)y * GX;

        uint32_t regs[5][2][2];
        #pragma unroll
        for (int kstep = 0; kstep < 2; kstep++) {
            #pragma unroll
            for (int khi = 0; khi < 2; khi++) {
                int xb = kt * 32 + kstep * 16 + khi * 8 + 2 * tg;
                float4 e0 = er[xb];
                float4 e1 = er[xb + 1];
                float pe[5], po[5];
                pe[0] = (e0.x + e0.y + e0.z + e0.w) * 0.25f;
                po[0] = (e1.x + e1.y + e1.z + e1.w) * 0.25f;
                pe[1] = (e0.x - e0.y + e0.z - e0.w) * 0.25f;
                po[1] = (e1.x - e1.y + e1.z - e1.w) * 0.25f;
                pe[2] = (e0.x - e0.z) * 0.5f;   po[2] = (e1.x - e1.z) * 0.5f;
                pe[3] = (e0.w - e0.y) * 0.5f;   po[3] = (e1.w - e1.y) * 0.5f;
                pe[4] = -pe[3];                 po[4] = -po[3];
                #pragma unroll
                for (int p = 0; p < 5; p++) regs[p][kstep][khi] = pack_h2(pe[p], po[p]);
            }
        }
        uint32_t* tile = g_E + (size_t)(yt * 32 + kt) * E_TILE_U32;
        #pragma unroll
        for (int p = 0; p < 5; p++)
            #pragma unroll
            for (int kstep = 0; kstep < 2; kstep++) {
                int idx = (((p * 4 + (nt >> 1)) * 2 + kstep) * 32 + lane) * 4 + (nt & 1) * 2;
                *reinterpret_cast<uint2*>(tile + idx) =
                    make_uint2(regs[p][kstep][0], regs[p][kstep][1]);
            }
    }
}

// ---------------------------------------------------------------------------
// GEMM: CTA owns 2 bmt x 2 yt sub-tiles. Per sub-tile 128b x 64 gy-blocks;
// 8 warps (4m x 2n), warp 32b x 32gy. 4-stage bulk+mbarrier ring, depth 3.
// ---------------------------------------------------------------------------
#define STAGE_U32 (A_TILE_U32 + E_TILE_U32)       // 13312 (53248 B)
#define STAGES 4
#define HDR_U32 256                               // 1024 B header
#define SMEM_BYTES ((HDR_U32 + STAGES * STAGE_U32) * 4)   // 214016

__global__ void __launch_bounds__(256, 1) gemm_freq_kernel(float* __restrict__ out) {
    extern __shared__ uint32_t smem[];
    const uint32_t sbase  = smem_u32(smem);
    const uint32_t full0  = sbase;            // full[s]  at +8s
    const uint32_t empty0 = sbase + 32;       // empty[s] at +8s
    const uint32_t stage0 = sbase + HDR_U32 * 4;

    const int tid  = threadIdx.x;
    const int ytp  = blockIdx.x;   // 0..7
    const int bmtp = blockIdx.y;   // 0..15

    const int warp  = tid >> 5;
    const int lane  = tid & 31;
    const int g     = lane >> 2;
    const int tg    = lane & 3;
    const int warpM = warp & 3;
    const int warpN = warp >> 2;

    if (tid == 0) {
        #pragma unroll
        for (int s = 0; s < STAGES; s++) {
            mbar_init(full0 + 8 * s, 1);
            mbar_init(empty0 + 8 * s, 8);
        }
    }
    __syncthreads();

    auto produce = [&](int gi) {
        int t2 = gi >> 5, kt2 = gi & 31;
        int bsel = t2 >> 1, ysel = bsel ^ (t2 & 1);
        const uint32_t* sA = g_U + (size_t)((bmtp * 2 + bsel) * 32 + kt2) * A_TILE_U32;
        const uint32_t* sE = g_E + (size_t)((ytp * 2 + ysel) * 32 + kt2) * E_TILE_U32;
        int s2 = gi & (STAGES - 1), r2 = gi >> 2;
        if (r2 >= 1) mbar_wait(empty0 + 8 * s2, (uint32_t)(r2 - 1) & 1u);
        uint32_t fb = full0 + 8 * s2;
        mbar_expect_tx(fb, STAGE_U32 * 4);
        uint32_t sa = stage0 + s2 * (STAGE_U32 * 4);
        bulk_g2s(sa, sA, A_TILE_U32 * 4, fb);
        bulk_g2s(sa + A_TILE_U32 * 4, sE, E_TILE_U32 * 4, fb);
    };

    if (tid == 0) { produce(0); produce(1); produce(2); }

    #define MMA(ACC, AF, B0, B1)                                                  \
        asm volatile(                                                             \
            "mma.sync.aligned.m16n8k16.row.col.f32.f16.f16.f32 "                  \
            "{%0,%1,%2,%3}, {%4,%5,%6,%7}, {%8,%9}, {%0,%1,%2,%3};\n"             \
            : "+f"((ACC)[0]), "+f"((ACC)[1]), "+f"((ACC)[2]), "+f"((ACC)[3])      \
            : "r"((AF).x), "r"((AF).y), "r"((AF).z), "r"((AF).w),                 \
              "r"(B0), "r"(B1))

    for (int t = 0; t < 4; t++) {
        const int bsel = t >> 1, ysel = bsel ^ (t & 1);
        const int bm0  = (bmtp * 2 + bsel) * 128;
        const int bgy0 = (ytp * 2 + ysel) * 64;

        float acc[4][2][4][4];   // [set][mi][ni][frag]  0=F0 1=F2 2=F1r 3=F1i
        #pragma unroll
        for (int s = 0; s < 4; s++)
            #pragma unroll
            for (int mi = 0; mi < 2; mi++)
                #pragma unroll
                for (int ni = 0; ni < 4; ni++)
                    #pragma unroll
                    for (int q = 0; q < 4; q++) acc[s][mi][ni][q] = 0.0f;

        for (int kt = 0; kt < 32; kt++) {
            int gi = t * 32 + kt;
            if (tid == 0 && gi + 3 < 128) produce(gi + 3);

            int s = gi & (STAGES - 1);
            mbar_wait(full0 + 8 * s, (uint32_t)(gi >> 2) & 1u);

            const uint32_t* base = smem + HDR_U32 + s * STAGE_U32;
            const uint4* A4 = reinterpret_cast<const uint4*>(base);
            const uint4* E4 = reinterpret_cast<const uint4*>(base + A_TILE_U32);

            #pragma unroll
            for (int kstep = 0; kstep < 2; kstep++) {
                uint4 uf[4][2];
                #pragma unroll
                for (int c = 0; c < 4; c++)
                    #pragma unroll
                    for (int mi = 0; mi < 2; mi++)
                        uf[c][mi] = A4[((c * 8 + warpM * 2 + mi) * 2 + kstep) * 32 + lane];

                uint2 ef[5][4];
                #pragma unroll
                for (int p = 0; p < 5; p++)
                    #pragma unroll
                    for (int nip = 0; nip < 2; nip++) {
                        uint4 e4 = E4[((p * 4 + warpN * 2 + nip) * 2 + kstep) * 32 + lane];
                        ef[p][2 * nip]     = make_uint2(e4.x, e4.y);
                        ef[p][2 * nip + 1] = make_uint2(e4.z, e4.w);
                    }

                #pragma unroll
                for (int ni = 0; ni < 4; ni++) {
                    #pragma unroll
                    for (int mi = 0; mi < 2; mi++) {
                        MMA(acc[0][mi][ni], uf[0][mi], ef[0][ni].x, ef[0][ni].y);
                        MMA(acc[1][mi][ni], uf[3][mi], ef[1][ni].x, ef[1][ni].y);
                        MMA(acc[2][mi][ni], uf[1][mi], ef[2][ni].x, ef[2][ni].y);
                        MMA(acc[2][mi][ni], uf[2][mi], ef[4][ni].x, ef[4][ni].y);
                        MMA(acc[3][mi][ni], uf[1][mi], ef[3][ni].x, ef[3][ni].y);
                        MMA(acc[3][mi][ni], uf[2][mi], ef[2][ni].x, ef[2][ni].y);
                    }
                }
            }
            if (lane == 0) mbar_arrive(empty0 + 8 * s);
        }

        // Epilogue: inverse-DFT butterfly, float4 stores.
        #pragma unroll
        for (int mi = 0; mi < 2; mi++) {
            #pragma unroll
            for (int ni = 0; ni < 4; ni++) {
                #pragma unroll
                for (int h = 0; h < 2; h++) {
                    #pragma unroll
                    for (int q = 0; q < 2; q++) {
                        int row = bm0 + warpM * 32 + mi * 16 + g + h * 8;
                        int gy  = bgy0 + warpN * 32 + ni * 8 + 2 * tg + q;
                        float F0  = acc[0][mi][ni][2 * h + q];
                        float F2  = acc[1][mi][ni][2 * h + q];
                        float F1r = acc[2][mi][ni][2 * h + q];
                        float F1i = acc[3][mi][ni][2 * h + q];
                        float4 o;
                        o.x = F0 + F1r + F2;
                        o.y = F0 - F1i - F2;
                        o.z = F0 - F1r + F2;
                        o.w = F0 + F1i - F2;
                        *reinterpret_cast<float4*>(out + (size_t)row * N_DIM + 4 * gy) = o;
                    }
                }
            }
        }
    }
    #undef MMA
}

// ---------------------------------------------------------------------------
extern "C" void kernel_launch(void* const* d_in, const int* in_sizes, int n_in,
                              void* d_out, int out_size) {
    const float* x   = (const float*)d_in[0];   // (4096, 4096) f32
    const float* eig = (const float*)d_in[1];   // (1024, 1024, 4) f32
    float* out       = (float*)d_out;           // (4096, 4096) f32

    cudaFuncSetAttribute(gemm_freq_kernel,
                         cudaFuncAttributeMaxDynamicSharedMemorySize, SMEM_BYTES);

    transform_kernel<<<1536, 256>>>(x, eig);

    dim3 grid(8, 16);   // 128 CTAs, each 2 bmt x 2 yt sub-tiles => single wave
    gemm_freq_kernel<<<grid, 256, SMEM_BYTES>>>(out);
    (void)in_sizes; (void)n_in; (void)out_size;
}